// round 13
// baseline (speedup 1.0000x reference)
#include <cuda_runtime.h>
#include <cuda_fp16.h>
#include <math.h>
#include <stdint.h>

// Problem dims (fixed by the dataset)
#define NB 64
#define NO 1024
#define NI 1024
#define OT 4                       // o-rows per block
#define MAIN_BLOCKS (NO/OT)        // 256

// Dynamic smem layout (bytes)
#define SMEM_EPS0   0              // stage 0: 2 b x 4 o x 4KB = 32KB
#define SMEM_EPS1   32768          // stage 1: 32KB
#define SMEM_MU     65536          // 4096 floats = 16KB
#define SMEM_SG     81920          // 16KB
#define SMEM_MBAR   98304          // 2 x 8B mbarriers
#define SMEM_DRED   98320          // 256 doubles = 2048B (8-aligned)
#define SMEM_RED    100368         // 256 floats = 1024B
#define SMEM_LAST   101392         // int
#define SMEM_TOTAL  101408

// Scratch (no allocations allowed -> __device__ globals)
__device__ double g_part[MAIN_BLOCKS][5];
__device__ int    g_counter;   // zero-init; reset by last block each run

// ---- packed f32x2 helpers (Blackwell FFMA2 path, PTX-only) ------------------
__device__ __forceinline__ unsigned long long f2_fma(unsigned long long a,
                                                     unsigned long long b,
                                                     unsigned long long c) {
    unsigned long long d;
    asm("fma.rn.f32x2 %0, %1, %2, %3;" : "=l"(d) : "l"(a), "l"(b), "l"(c));
    return d;
}
__device__ __forceinline__ unsigned long long f2_mul(unsigned long long a,
                                                     unsigned long long b) {
    unsigned long long d;
    asm("mul.rn.f32x2 %0, %1, %2;" : "=l"(d) : "l"(a), "l"(b));
    return d;
}
__device__ __forceinline__ unsigned long long f2_add(unsigned long long a,
                                                     unsigned long long b) {
    unsigned long long d;
    asm("add.rn.f32x2 %0, %1, %2;" : "=l"(d) : "l"(a), "l"(b));
    return d;
}
__device__ __forceinline__ unsigned long long f2_pack(float lo, float hi) {
    unsigned long long d;
    asm("mov.b64 %0, {%1, %2};" : "=l"(d) : "f"(lo), "f"(hi));
    return d;
}
__device__ __forceinline__ void f2_unpack(unsigned long long v, float& lo, float& hi) {
    asm("mov.b64 {%0, %1}, %2;" : "=f"(lo), "=f"(hi) : "l"(v));
}

// ---- bulk-async + mbarrier primitives ---------------------------------------
__device__ __forceinline__ uint32_t smem_u32(const void* p) {
    uint32_t a;
    asm("{ .reg .u64 t; cvta.to.shared.u64 t, %1; cvt.u32.u64 %0, t; }"
        : "=r"(a) : "l"(p));
    return a;
}
__device__ __forceinline__ void mbar_init(uint32_t mbar, uint32_t cnt) {
    asm volatile("mbarrier.init.shared.b64 [%0], %1;" :: "r"(mbar), "r"(cnt) : "memory");
}
__device__ __forceinline__ void mbar_expect_tx(uint32_t mbar, uint32_t bytes) {
    asm volatile("mbarrier.arrive.expect_tx.shared.b64 _, [%0], %1;"
                 :: "r"(mbar), "r"(bytes) : "memory");
}
__device__ __forceinline__ void mbar_wait(uint32_t mbar, uint32_t parity) {
    asm volatile(
        "{\n\t"
        ".reg .pred P;\n\t"
        "WAIT_%=:\n\t"
        "mbarrier.try_wait.parity.acquire.cta.shared::cta.b64 P, [%0], %1, 0x989680;\n\t"
        "@P bra.uni DONE_%=;\n\t"
        "bra.uni WAIT_%=;\n\t"
        "DONE_%=:\n\t"
        "}"
        :: "r"(mbar), "r"(parity) : "memory");
}
__device__ __forceinline__ void bulk_cp(uint32_t dst, const void* src,
                                        uint32_t bytes, uint32_t mbar) {
    asm volatile(
        "cp.async.bulk.shared::cluster.global.mbarrier::complete_tx::bytes "
        "[%0], [%1], %2, [%3];"
        :: "r"(dst), "l"(src), "r"(bytes), "r"(mbar) : "memory");
}

// ---------------------------------------------------------------------------
// Main kernel: eps streamed via cp.async.bulk into a 2-stage smem ring.
// Load concurrency decoupled from registers entirely (this round's variable).
// ---------------------------------------------------------------------------
__global__ void main_kernel(
    const float* __restrict__ x,
    const float* __restrict__ wmu,
    const float* __restrict__ wrho,
    const float* __restrict__ bmu,
    const float* __restrict__ brho,
    const float* __restrict__ epsw,
    const float* __restrict__ epsb,
    float* __restrict__ out)
{
    extern __shared__ char smem[];
    float*  mu_s = reinterpret_cast<float*>(smem + SMEM_MU);
    float*  sg_s = reinterpret_cast<float*>(smem + SMEM_SG);
    float*  red  = reinterpret_cast<float*>(smem + SMEM_RED);
    double* dred = reinterpret_cast<double*>(smem + SMEM_DRED);
    int*    lastp= reinterpret_cast<int*>(smem + SMEM_LAST);
    uint32_t sbase = smem_u32(smem);
    uint32_t mbar0 = sbase + SMEM_MBAR;
    uint32_t mbar1 = sbase + SMEM_MBAR + 8;

    const float KP   = 6.2146080984221914f;   // -log(0.002)
    const float C2   = 124999.5f;             // 1/(2*0.002^2) - 0.5
    const float NC2L = -180336.15876359287f;  // -C2 * log2(e)
    const float KPL2 = 8.96578433024671f;     // KP * log2(e)
    const unsigned long long NC2L2 = f2_pack(NC2L, NC2L);
    const unsigned long long KPL22 = f2_pack(KPL2, KPL2);
    const unsigned long long ONE2  = f2_pack(1.f, 1.f);

    int t      = threadIdx.x;
    int o_base = blockIdx.x * OT;

    // init mbarriers, then issue stage 0 (b=0,1) before staging mu/sigma
    if (t == 0) {
        mbar_init(mbar0, 1);
        mbar_init(mbar1, 1);
    }
    __syncthreads();
    if (t == 0) {
        mbar_expect_tx(mbar0, 32768);
        bulk_cp(sbase + SMEM_EPS0,
                epsw + ((size_t)(0 * NO + o_base) << 10), 16384, mbar0);
        bulk_cp(sbase + SMEM_EPS0 + 16384,
                epsw + ((size_t)(1 * NO + o_base) << 10), 16384, mbar0);
    }

    // stage mu and sigma=softplus(rho) into smem, accumulating sum(log sigma)
    float lsig = 0.f;
#pragma unroll
    for (int k = 0; k < 4; k++) {
        int f   = t + k * 256;
        int row = f >> 8;
        int col = (f & 255) << 2;
        float4 m = *reinterpret_cast<const float4*>(wmu + (size_t)(o_base + row) * NI + col);
        float4 r = *reinterpret_cast<const float4*>(wrho + (size_t)(o_base + row) * NI + col);
        float4 s;
        s.x = log1pf(__expf(r.x));
        s.y = log1pf(__expf(r.y));
        s.z = log1pf(__expf(r.z));
        s.w = log1pf(__expf(r.w));
        lsig += __logf(s.x) + __logf(s.y) + __logf(s.z) + __logf(s.w);
        *reinterpret_cast<float4*>(&mu_s[row * NI + col]) = m;
        *reinterpret_cast<float4*>(&sg_s[row * NI + col]) = s;
    }
    __syncthreads();

    int warp  = t >> 5, lane = t & 31;
    int oi    = warp & 3;         // fixed o-row for this warp
    int bslot = warp >> 2;        // which of the 2 staged b's
    int o     = o_base + oi;

    const float* mu_row = mu_s + oi * NI;
    const float* sg_row = sg_s + oi * NI;

    // per-warp bias constants
    float bs   = log1pf(__expf(brho[o]));
    float bmo  = bmu[o];
    float nlbs = -__logf(bs);

    unsigned long long stA = 0ull;   // sum w^2
    unsigned long long seA = 0ull;   // sum eps^2
    unsigned long long d2;           // packed dot accumulator
    float sr = 0.f;                  // sum softplus(df)
    float pb = 0.f;                  // bias posterior extras
    float st_bias = 0.f;             // bias w^2

#define BODY2(E2, M2, S2, X2, PQ)                                 \
    {                                                             \
        unsigned long long w2 = f2_fma((S2), (E2), (M2));         \
        d2  = f2_fma(w2, (X2), d2);                               \
        seA = f2_fma((E2), (E2), seA);                            \
        unsigned long long t2 = f2_mul(w2, w2);                   \
        stA = f2_add(stA, t2);                                    \
        unsigned long long u2 = f2_fma(t2, NC2L2, KPL22);         \
        float ul, uh; f2_unpack(u2, ul, uh);                      \
        float2 ef = __half22float2(h2exp2(__floats2half2_rn(ul, uh))); \
        unsigned long long ee = f2_pack(ef.x, ef.y);              \
        PQ = f2_fma(PQ, ee, PQ);                                  \
    }

    for (int m = 0; m < 32; m++) {
        int s = m & 1;

        // issue stage m+1 into the other buffer (free since iter m-1 ended
        // with __syncthreads): register-free DMA, deep overlap
        if (t == 0 && m < 31) {
            uint32_t mb  = s ? mbar0 : mbar1;
            uint32_t dst = sbase + (s ? SMEM_EPS0 : SMEM_EPS1);
            int bn = 2 * (m + 1);
            mbar_expect_tx(mb, 32768);
            bulk_cp(dst,
                    epsw + ((size_t)(bn * NO + o_base) << 10), 16384, mb);
            bulk_cp(dst + 16384,
                    epsw + ((size_t)((bn + 1) * NO + o_base) << 10), 16384, mb);
        }

        // wait for this stage's data
        mbar_wait(s ? mbar1 : mbar0, (m >> 1) & 1);

        int b = 2 * m + bslot;
        const float* erow = reinterpret_cast<const float*>(
            smem + (s ? SMEM_EPS1 : SMEM_EPS0) + bslot * 16384 + oi * 4096);
        const ulonglong2* xr = reinterpret_cast<const ulonglong2*>(x + (size_t)b * NI);

        d2 = 0ull;
        unsigned long long pA = ONE2;
#pragma unroll
        for (int k = 0; k < 8; k++) {
            int idx = k * 32 + lane;
            ulonglong2 e  = *reinterpret_cast<const ulonglong2*>(erow + idx * 4);
            ulonglong2 xv = xr[idx];
            ulonglong2 mm = *reinterpret_cast<const ulonglong2*>(mu_row + idx * 4);
            ulonglong2 ss = *reinterpret_cast<const ulonglong2*>(sg_row + idx * 4);
            BODY2(e.x, mm.x, ss.x, xv.x, pA)
            BODY2(e.y, mm.y, ss.y, xv.y, pA)
            if (k == 3) {                      // close chains: <=501^4 per half
                float al, ah;
                f2_unpack(pA, al, ah);
                sr += __logf(al * ah);
                pA = ONE2;
            }
        }
        {
            float al, ah;
            f2_unpack(pA, al, ah);
            sr += __logf(al * ah);
        }

        // warp-reduce dot, add sampled bias, emit out[b][o]
        float vl, vh;
        f2_unpack(d2, vl, vh);
        float v = vl + vh;
#pragma unroll
        for (int off = 16; off; off >>= 1)
            v += __shfl_down_sync(0xffffffffu, v, off);
        if (lane == 0) {
            float eb = epsb[b * NO + o];
            float bv = fmaf(bs, eb, bmo);
            out[b * NO + o] = v + bv;
            pb += nlbs - 0.5f * eb * eb;
            float tb = bv * bv;
            st_bias += tb;
            float dfb = fmaf(tb, -C2, KP);
            sr += fmaxf(dfb, 0.f);
            float fdb = fabsf(dfb);
            if (fdb < 15.f) sr += log1pf(__expf(-fdb));
        }

        __syncthreads();   // all warps done with buffer s before its reuse
    }
#undef BODY2

    // collapse packed accumulators to scalars
    float s0l, s0h, s1l, s1h;
    f2_unpack(stA, s0l, s0h);
    f2_unpack(seA, s1l, s1h);
    float st = s0l + s0h + st_bias;
    float se = s1l + s1h;

    // block reduction of the 5 accumulators -> deterministic double partials
    float acc[5] = {st, sr, se, pb, lsig};
#pragma unroll
    for (int q = 0; q < 5; q++) {
        __syncthreads();
        red[t] = acc[q];
        __syncthreads();
        for (int s = 128; s > 0; s >>= 1) {
            if (t < s) red[t] += red[t + s];
            __syncthreads();
        }
        if (t == 0) g_part[blockIdx.x][q] = (double)red[0];
    }

    // ---- last-block finalize (deterministic fixed-order double reduction) ----
    __threadfence();
    if (t == 0) {
        int old = atomicAdd(&g_counter, 1);
        *lastp = (old == MAIN_BLOCKS - 1) ? 1 : 0;
    }
    __syncthreads();
    if (!*lastp) return;
    __threadfence();

    double a[5] = {0, 0, 0, 0, 0};
    for (int i = t; i < MAIN_BLOCKS; i += 256)
#pragma unroll
        for (int q = 0; q < 5; q++) a[q] += g_part[i][q];

    double tot[5];
#pragma unroll
    for (int q = 0; q < 5; q++) {
        __syncthreads();
        dred[t] = a[q];
        __syncthreads();
        for (int s = 128; s > 0; s >>= 1) {
            if (t < s) dred[t] += dred[t + s];
            __syncthreads();
        }
        tot[q] = dred[0];
    }
    if (t == 0) {
        const double c   = 0.9189385332046727;     // log(sqrt(2*pi))
        const double l05 = -0.6931471805599453;    // log(0.5)
        const double Nw  = 67108864.0;             // B*O*I
        const double Nb2 = 65536.0;                // B*O
        double lp    = (Nw + Nb2) * (l05 - c) - 0.5 * tot[0] + tot[1];
        // each o-tile staged exactly once -> coefficient B = 64
        double lpost = -(Nw + Nb2) * c - 64.0 * tot[4] - 0.5 * tot[2] + tot[3];
        out[NB * NO]     = (float)lp;
        out[NB * NO + 1] = (float)lpost;
        g_counter = 0;                              // reset for next graph replay
    }
}

// ---------------------------------------------------------------------------
extern "C" void kernel_launch(void* const* d_in, const int* in_sizes, int n_in,
                              void* d_out, int out_size)
{
    const float* x    = (const float*)d_in[0];   // (64,1024)
    const float* wmu  = (const float*)d_in[1];   // (1024,1024)
    const float* wrho = (const float*)d_in[2];   // (1024,1024)
    const float* bmu  = (const float*)d_in[3];   // (1024,)
    const float* brho = (const float*)d_in[4];   // (1024,)
    const float* epsw = (const float*)d_in[5];   // (64,1024,1024)
    const float* epsb = (const float*)d_in[6];   // (64,1024)
    float* out = (float*)d_out;                  // 65536 + 2

    cudaFuncSetAttribute(main_kernel,
                         cudaFuncAttributeMaxDynamicSharedMemorySize, SMEM_TOTAL);
    main_kernel<<<MAIN_BLOCKS, 256, SMEM_TOTAL>>>(x, wmu, wrho, bmu, brho,
                                                  epsw, epsb, out);
}

// round 14
// speedup vs baseline: 1.1124x; 1.1124x over previous
#include <cuda_runtime.h>
#include <cuda_fp16.h>
#include <math.h>
#include <stdint.h>

// Problem dims (fixed by the dataset)
#define NB 64
#define NO 1024
#define NI 1024
#define OT 4                       // o-rows per block
#define MAIN_BLOCKS (NO/OT)        // 256

// Dynamic smem layout (bytes)
#define SMEM_EPS    0              // 4-stage ring, 16KB each = 64KB
#define SMEM_MU     65536          // 16KB
#define SMEM_SG     81920          // 16KB
#define SMEM_MBAR   98304          // 4 x 8B
#define SMEM_PDOT   98336          // 2 x 8 floats (parity double buffer)
#define SMEM_RED    98400          // 256 floats
#define SMEM_DRED   99424          // 256 doubles (8-aligned)
#define SMEM_LAST   101472         // int
#define SMEM_TOTAL  101504

// Scratch (no allocations allowed -> __device__ globals)
__device__ double g_part[MAIN_BLOCKS][5];
__device__ int    g_counter;   // zero-init; reset by last block each run

// ---- packed f32x2 helpers (Blackwell FFMA2 path, PTX-only) ------------------
__device__ __forceinline__ unsigned long long f2_fma(unsigned long long a,
                                                     unsigned long long b,
                                                     unsigned long long c) {
    unsigned long long d;
    asm("fma.rn.f32x2 %0, %1, %2, %3;" : "=l"(d) : "l"(a), "l"(b), "l"(c));
    return d;
}
__device__ __forceinline__ unsigned long long f2_mul(unsigned long long a,
                                                     unsigned long long b) {
    unsigned long long d;
    asm("mul.rn.f32x2 %0, %1, %2;" : "=l"(d) : "l"(a), "l"(b));
    return d;
}
__device__ __forceinline__ unsigned long long f2_add(unsigned long long a,
                                                     unsigned long long b) {
    unsigned long long d;
    asm("add.rn.f32x2 %0, %1, %2;" : "=l"(d) : "l"(a), "l"(b));
    return d;
}
__device__ __forceinline__ unsigned long long f2_pack(float lo, float hi) {
    unsigned long long d;
    asm("mov.b64 %0, {%1, %2};" : "=l"(d) : "f"(lo), "f"(hi));
    return d;
}
__device__ __forceinline__ void f2_unpack(unsigned long long v, float& lo, float& hi) {
    asm("mov.b64 {%0, %1}, %2;" : "=f"(lo), "=f"(hi) : "l"(v));
}

// ---- bulk-async + mbarrier primitives ---------------------------------------
__device__ __forceinline__ uint32_t smem_u32(const void* p) {
    uint32_t a;
    asm("{ .reg .u64 t; cvta.to.shared.u64 t, %1; cvt.u32.u64 %0, t; }"
        : "=r"(a) : "l"(p));
    return a;
}
__device__ __forceinline__ void mbar_init(uint32_t mbar, uint32_t cnt) {
    asm volatile("mbarrier.init.shared.b64 [%0], %1;" :: "r"(mbar), "r"(cnt) : "memory");
}
__device__ __forceinline__ void mbar_expect_tx(uint32_t mbar, uint32_t bytes) {
    asm volatile("mbarrier.arrive.expect_tx.shared.b64 _, [%0], %1;"
                 :: "r"(mbar), "r"(bytes) : "memory");
}
__device__ __forceinline__ void mbar_wait(uint32_t mbar, uint32_t parity) {
    asm volatile(
        "{\n\t"
        ".reg .pred P;\n\t"
        "WAIT_%=:\n\t"
        "mbarrier.try_wait.parity.acquire.cta.shared::cta.b64 P, [%0], %1, 0x989680;\n\t"
        "@P bra.uni DONE_%=;\n\t"
        "bra.uni WAIT_%=;\n\t"
        "DONE_%=:\n\t"
        "}"
        :: "r"(mbar), "r"(parity) : "memory");
}
__device__ __forceinline__ void bulk_cp(uint32_t dst, const void* src,
                                        uint32_t bytes, uint32_t mbar) {
    asm volatile(
        "cp.async.bulk.shared::cluster.global.mbarrier::complete_tx::bytes "
        "[%0], [%1], %2, [%3];"
        :: "r"(dst), "l"(src), "r"(bytes), "r"(mbar) : "memory");
}

// ---------------------------------------------------------------------------
// Main kernel: eps streamed via cp.async.bulk, 4-stage / 16KB ring with
// prefetch distance 3 (48KB in flight per block). Stage = one batch row b:
// eps[b][o_base:o_base+4][:] is ONE contiguous 16KB block. All 8 warps
// consume the stage: warp w -> o-row (w&3), half (w>>2).
// ---------------------------------------------------------------------------
__global__ __launch_bounds__(256) void main_kernel(
    const float* __restrict__ x,
    const float* __restrict__ wmu,
    const float* __restrict__ wrho,
    const float* __restrict__ bmu,
    const float* __restrict__ brho,
    const float* __restrict__ epsw,
    const float* __restrict__ epsb,
    float* __restrict__ out)
{
    extern __shared__ char smem[];
    float*  mu_s  = reinterpret_cast<float*>(smem + SMEM_MU);
    float*  sg_s  = reinterpret_cast<float*>(smem + SMEM_SG);
    float*  pdot  = reinterpret_cast<float*>(smem + SMEM_PDOT);
    float*  red   = reinterpret_cast<float*>(smem + SMEM_RED);
    double* dred  = reinterpret_cast<double*>(smem + SMEM_DRED);
    int*    lastp = reinterpret_cast<int*>(smem + SMEM_LAST);
    uint32_t sbase = smem_u32(smem);

    const float KP   = 6.2146080984221914f;   // -log(0.002)
    const float C2   = 124999.5f;             // 1/(2*0.002^2) - 0.5
    const float NC2L = -180336.15876359287f;  // -C2 * log2(e)
    const float KPL2 = 8.96578433024671f;     // KP * log2(e)
    const unsigned long long NC2L2 = f2_pack(NC2L, NC2L);
    const unsigned long long KPL22 = f2_pack(KPL2, KPL2);
    const unsigned long long ONE2  = f2_pack(1.f, 1.f);

    int t      = threadIdx.x;
    int o_base = blockIdx.x * OT;

    // init ring mbarriers, then prefetch stages 0..2 before mu/sg staging
    if (t == 0) {
#pragma unroll
        for (int s = 0; s < 4; s++) mbar_init(sbase + SMEM_MBAR + 8 * s, 1);
    }
    __syncthreads();
    if (t == 0) {
#pragma unroll
        for (int s = 0; s < 3; s++) {
            uint32_t mb = sbase + SMEM_MBAR + 8 * s;
            mbar_expect_tx(mb, 16384);
            bulk_cp(sbase + SMEM_EPS + s * 16384,
                    epsw + ((size_t)(s * NO + o_base) << 10), 16384, mb);
        }
    }

    // stage mu and sigma=softplus(rho) into smem, accumulating sum(log sigma)
    float lsig = 0.f;
#pragma unroll
    for (int k = 0; k < 4; k++) {
        int f   = t + k * 256;
        int row = f >> 8;
        int col = (f & 255) << 2;
        float4 m = *reinterpret_cast<const float4*>(wmu + (size_t)(o_base + row) * NI + col);
        float4 r = *reinterpret_cast<const float4*>(wrho + (size_t)(o_base + row) * NI + col);
        float4 s;
        s.x = log1pf(__expf(r.x));
        s.y = log1pf(__expf(r.y));
        s.z = log1pf(__expf(r.z));
        s.w = log1pf(__expf(r.w));
        lsig += __logf(s.x) + __logf(s.y) + __logf(s.z) + __logf(s.w);
        *reinterpret_cast<float4*>(&mu_s[row * NI + col]) = m;
        *reinterpret_cast<float4*>(&sg_s[row * NI + col]) = s;
    }
    __syncthreads();

    int warp = t >> 5, lane = t & 31;
    int oi   = warp & 3;          // o-row within tile
    int half = warp >> 2;         // half-row ownership
    int col0 = half * 128;        // float4 base index within the 1024-float row

    const float* mu_row = mu_s + oi * NI;
    const float* sg_row = sg_s + oi * NI;

    // emission constants for threads t<4 (thread t emits o = o_base+t)
    float bs_t = 0.f, bmo_t = 0.f, nlbs_t = 0.f;
    if (t < 4) {
        int o  = o_base + t;
        bs_t   = log1pf(__expf(brho[o]));
        bmo_t  = bmu[o];
        nlbs_t = -__logf(bs_t);
    }

    unsigned long long stA = 0ull;   // sum w^2
    unsigned long long seA = 0ull;   // sum eps^2
    unsigned long long d2;           // packed dot accumulator
    float sr = 0.f;                  // sum softplus(df)
    float pb = 0.f;                  // bias posterior extras
    float st_bias = 0.f;             // bias w^2

#define BODY2(E2, M2, S2, X2, PQ)                                 \
    {                                                             \
        unsigned long long w2 = f2_fma((S2), (E2), (M2));         \
        d2  = f2_fma(w2, (X2), d2);                               \
        seA = f2_fma((E2), (E2), seA);                            \
        unsigned long long t2 = f2_mul(w2, w2);                   \
        stA = f2_add(stA, t2);                                    \
        unsigned long long u2 = f2_fma(t2, NC2L2, KPL22);         \
        float ul, uh; f2_unpack(u2, ul, uh);                      \
        float2 ef = __half22float2(h2exp2(__floats2half2_rn(ul, uh))); \
        unsigned long long ee = f2_pack(ef.x, ef.y);              \
        PQ = f2_fma(PQ, ee, PQ);                                  \
    }

    for (int m = 0; m < NB; m++) {
        int sl = m & 3;

        // keep prefetch distance 3: issue stage m+3 into slot (m+3)&3
        // (that slot's previous stage m-1 was fully consumed before the
        //  __syncthreads at the end of iteration m-1)
        if (t == 0 && m + 3 < NB) {
            int s2 = (m + 3) & 3;
            uint32_t mb = sbase + SMEM_MBAR + 8 * s2;
            mbar_expect_tx(mb, 16384);
            bulk_cp(sbase + SMEM_EPS + s2 * 16384,
                    epsw + ((size_t)((m + 3) * NO + o_base) << 10), 16384, mb);
        }

        // wait for stage m (slot use #(m>>2) -> parity)
        mbar_wait(sbase + SMEM_MBAR + 8 * sl, (m >> 2) & 1);

        int b = m;
        const float* erow = reinterpret_cast<const float*>(
            smem + SMEM_EPS + sl * 16384 + oi * 4096);
        const ulonglong2* xr = reinterpret_cast<const ulonglong2*>(x + (size_t)b * NI);

        d2 = 0ull;
        unsigned long long pA = ONE2;     // 8 factors/slot this stage
#pragma unroll
        for (int k = 0; k < 4; k++) {
            int idx = col0 + k * 32 + lane;
            ulonglong2 e  = *reinterpret_cast<const ulonglong2*>(erow + idx * 4);
            ulonglong2 xv = xr[idx];
            ulonglong2 mm = *reinterpret_cast<const ulonglong2*>(mu_row + idx * 4);
            ulonglong2 ss = *reinterpret_cast<const ulonglong2*>(sg_row + idx * 4);
            BODY2(e.x, mm.x, ss.x, xv.x, pA)
            BODY2(e.y, mm.y, ss.y, xv.y, pA)
        }
        {
            float al, ah;
            f2_unpack(pA, al, ah);
            sr += __logf(al * ah);        // <= 501^8 * ... safe in f32
        }

        // half-row dot -> warp reduce -> parity-buffered smem combine
        float vl, vh;
        f2_unpack(d2, vl, vh);
        float v = vl + vh;
#pragma unroll
        for (int off = 16; off; off >>= 1)
            v += __shfl_down_sync(0xffffffffu, v, off);
        if (lane == 0) pdot[(m & 1) * 8 + oi * 2 + half] = v;

        __syncthreads();   // stage consumed + pdot visible

        if (t < 4) {       // thread t emits (b, o_base+t)
            float vv = pdot[(m & 1) * 8 + t * 2] + pdot[(m & 1) * 8 + t * 2 + 1];
            int   o  = o_base + t;
            float eb = epsb[b * NO + o];
            float bv = fmaf(bs_t, eb, bmo_t);
            out[b * NO + o] = vv + bv;
            pb += nlbs_t - 0.5f * eb * eb;
            float tb = bv * bv;
            st_bias += tb;
            float dfb = fmaf(tb, -C2, KP);
            sr += fmaxf(dfb, 0.f);
            float fdb = fabsf(dfb);
            if (fdb < 15.f) sr += log1pf(__expf(-fdb));
        }
    }
#undef BODY2

    // collapse packed accumulators to scalars
    float s0l, s0h, s1l, s1h;
    f2_unpack(stA, s0l, s0h);
    f2_unpack(seA, s1l, s1h);
    float st = s0l + s0h + st_bias;
    float se = s1l + s1h;

    // block reduction of the 5 accumulators -> deterministic double partials
    float acc[5] = {st, sr, se, pb, lsig};
#pragma unroll
    for (int q = 0; q < 5; q++) {
        __syncthreads();
        red[t] = acc[q];
        __syncthreads();
        for (int s = 128; s > 0; s >>= 1) {
            if (t < s) red[t] += red[t + s];
            __syncthreads();
        }
        if (t == 0) g_part[blockIdx.x][q] = (double)red[0];
    }

    // ---- last-block finalize (deterministic fixed-order double reduction) ----
    __threadfence();
    if (t == 0) {
        int old = atomicAdd(&g_counter, 1);
        *lastp = (old == MAIN_BLOCKS - 1) ? 1 : 0;
    }
    __syncthreads();
    if (!*lastp) return;
    __threadfence();

    double a[5] = {0, 0, 0, 0, 0};
    for (int i = t; i < MAIN_BLOCKS; i += 256)
#pragma unroll
        for (int q = 0; q < 5; q++) a[q] += g_part[i][q];

    double tot[5];
#pragma unroll
    for (int q = 0; q < 5; q++) {
        __syncthreads();
        dred[t] = a[q];
        __syncthreads();
        for (int s = 128; s > 0; s >>= 1) {
            if (t < s) dred[t] += dred[t + s];
            __syncthreads();
        }
        tot[q] = dred[0];
    }
    if (t == 0) {
        const double c   = 0.9189385332046727;     // log(sqrt(2*pi))
        const double l05 = -0.6931471805599453;    // log(0.5)
        const double Nw  = 67108864.0;             // B*O*I
        const double Nb2 = 65536.0;                // B*O
        double lp    = (Nw + Nb2) * (l05 - c) - 0.5 * tot[0] + tot[1];
        // each o-tile staged exactly once -> coefficient B = 64
        double lpost = -(Nw + Nb2) * c - 64.0 * tot[4] - 0.5 * tot[2] + tot[3];
        out[NB * NO]     = (float)lp;
        out[NB * NO + 1] = (float)lpost;
        g_counter = 0;                              // reset for next graph replay
    }
}

// ---------------------------------------------------------------------------
extern "C" void kernel_launch(void* const* d_in, const int* in_sizes, int n_in,
                              void* d_out, int out_size)
{
    const float* x    = (const float*)d_in[0];   // (64,1024)
    const float* wmu  = (const float*)d_in[1];   // (1024,1024)
    const float* wrho = (const float*)d_in[2];   // (1024,1024)
    const float* bmu  = (const float*)d_in[3];   // (1024,)
    const float* brho = (const float*)d_in[4];   // (1024,)
    const float* epsw = (const float*)d_in[5];   // (64,1024,1024)
    const float* epsb = (const float*)d_in[6];   // (64,1024)
    float* out = (float*)d_out;                  // 65536 + 2

    cudaFuncSetAttribute(main_kernel,
                         cudaFuncAttributeMaxDynamicSharedMemorySize, SMEM_TOTAL);
    main_kernel<<<MAIN_BLOCKS, 256, SMEM_TOTAL>>>(x, wmu, wrho, bmu, brho,
                                                  epsw, epsb, out);
}

// round 15
// speedup vs baseline: 1.3152x; 1.1823x over previous
#include <cuda_runtime.h>
#include <cuda_fp16.h>
#include <math.h>
#include <stdint.h>

// Problem dims (fixed by the dataset)
#define NB 64
#define NO 1024
#define NI 1024
#define OT 4                       // o-rows per item
#define GRID 296                   // 2 blocks x 148 SMs exactly
#define NITEMS 1024                // item = (o-tile, b-quarter): 4 o x 16 b

// Scratch (no allocations allowed -> __device__ globals)
__device__ double g_part[NITEMS * 8 * 5];   // per (item, warp): 5 partials
__device__ int    g_work;    // work-stealing counter (reset each run)
__device__ int    g_done;    // completion counter   (reset each run)

// ---- packed f32x2 helpers (Blackwell FFMA2 path, PTX-only) ------------------
__device__ __forceinline__ unsigned long long f2_fma(unsigned long long a,
                                                     unsigned long long b,
                                                     unsigned long long c) {
    unsigned long long d;
    asm("fma.rn.f32x2 %0, %1, %2, %3;" : "=l"(d) : "l"(a), "l"(b), "l"(c));
    return d;
}
__device__ __forceinline__ unsigned long long f2_mul(unsigned long long a,
                                                     unsigned long long b) {
    unsigned long long d;
    asm("mul.rn.f32x2 %0, %1, %2;" : "=l"(d) : "l"(a), "l"(b));
    return d;
}
__device__ __forceinline__ unsigned long long f2_add(unsigned long long a,
                                                     unsigned long long b) {
    unsigned long long d;
    asm("add.rn.f32x2 %0, %1, %2;" : "=l"(d) : "l"(a), "l"(b));
    return d;
}
__device__ __forceinline__ unsigned long long f2_pack(float lo, float hi) {
    unsigned long long d;
    asm("mov.b64 %0, {%1, %2};" : "=l"(d) : "f"(lo), "f"(hi));
    return d;
}
__device__ __forceinline__ void f2_unpack(unsigned long long v, float& lo, float& hi) {
    asm("mov.b64 {%0, %1}, %2;" : "=f"(lo), "=f"(hi) : "l"(v));
}

// ---------------------------------------------------------------------------
// Persistent main kernel: 296 blocks steal 1024 fine-grained items from a
// global counter -> per-SM byte loads equalize (kills the 15.6% wave-
// imbalance every prior round carried). Item math is block-independent and
// partials are stored per (item, warp) -> fully deterministic output.
// ---------------------------------------------------------------------------
__global__ __launch_bounds__(256, 2) void main_kernel(
    const float* __restrict__ x,
    const float* __restrict__ wmu,
    const float* __restrict__ wrho,
    const float* __restrict__ bmu,
    const float* __restrict__ brho,
    const float* __restrict__ epsw,
    const float* __restrict__ epsb,
    float* __restrict__ out)
{
    __shared__ float  mu_s[OT * NI];   // 16KB
    __shared__ float  sg_s[OT * NI];   // 16KB
    __shared__ double dred[256];       // 2KB (finalize)
    __shared__ int    s_item, s_last;

    const float KP   = 6.2146080984221914f;   // -log(0.002)
    const float C2   = 124999.5f;             // 1/(2*0.002^2) - 0.5
    const float NC2L = -180336.15876359287f;  // -C2 * log2(e)
    const float KPL2 = 8.96578433024671f;     // KP * log2(e)
    const unsigned long long NC2L2 = f2_pack(NC2L, NC2L);
    const unsigned long long KPL22 = f2_pack(KPL2, KPL2);
    const unsigned long long ONE2  = f2_pack(1.f, 1.f);

    int t    = threadIdx.x;
    int warp = t >> 5, lane = t & 31;

    for (;;) {
        // claim next item (also serves as the barrier guarding mu_s reuse)
        if (t == 0) s_item = atomicAdd(&g_work, 1);
        __syncthreads();
        int item = s_item;
        if (item >= NITEMS) break;

        int ot     = item >> 2;        // o-tile 0..255
        int bq     = item & 3;         // b-quarter 0..3
        int o_base = ot * OT;

        // stage mu and sigma=softplus(rho), accumulating sum(log sigma)
        float lsig = 0.f;
#pragma unroll
        for (int k = 0; k < 4; k++) {
            int f   = t + k * 256;
            int row = f >> 8;
            int col = (f & 255) << 2;
            float4 m = *reinterpret_cast<const float4*>(wmu + (size_t)(o_base + row) * NI + col);
            float4 r = *reinterpret_cast<const float4*>(wrho + (size_t)(o_base + row) * NI + col);
            float4 s;
            s.x = log1pf(__expf(r.x));
            s.y = log1pf(__expf(r.y));
            s.z = log1pf(__expf(r.z));
            s.w = log1pf(__expf(r.w));
            lsig += __logf(s.x) + __logf(s.y) + __logf(s.z) + __logf(s.w);
            *reinterpret_cast<float4*>(&mu_s[row * NI + col]) = m;
            *reinterpret_cast<float4*>(&sg_s[row * NI + col]) = s;
        }
        __syncthreads();

        // item-local accumulators
        unsigned long long stA = 0ull;   // sum w^2
        unsigned long long seA = 0ull;   // sum eps^2
        float sr  = 0.f;                 // sum softplus(df)
        float pb  = 0.f;                 // bias posterior extras
        float stb = 0.f;                 // bias w^2

        // per element-pair: w=fma(s,e,m); d+=w*x; se+=e*e; t=w*w; st+=t;
        // u=fma(t,-C2*l2e,KP*l2e); p=p*(1+2^u). exp via ex2.approx.f16x2
        // (8 factors/slot/j, each <=501 -> <=4.1e21, safe in f32).
#define BODY2(E2, M2, S2, X2, DI)                                 \
        {                                                         \
            unsigned long long w2 = f2_fma((S2), (E2), (M2));     \
            d2[DI] = f2_fma(w2, (X2), d2[DI]);                    \
            seA    = f2_fma((E2), (E2), seA);                     \
            unsigned long long t2 = f2_mul(w2, w2);               \
            stA = f2_add(stA, t2);                                \
            unsigned long long u2 = f2_fma(t2, NC2L2, KPL22);     \
            float ul, uh; f2_unpack(u2, ul, uh);                  \
            float2 ef = __half22float2(h2exp2(__floats2half2_rn(ul, uh))); \
            unsigned long long ee = f2_pack(ef.x, ef.y);          \
            pA = f2_fma(pA, ee, pA);                              \
        }

        for (int bb = 0; bb < 2; bb++) {
            int b = bq * 16 + bb * 8 + warp;
            unsigned long long d2[OT];
#pragma unroll
            for (int oi = 0; oi < OT; oi++) d2[oi] = 0ull;

            const float* xrow = x + (size_t)b * NI;
            const float* erow = epsw + (((size_t)(b * NO + o_base)) << 10);

            for (int j = 0; j < 8; j++) {
                int bi = (j << 7) + (lane << 2);
                ulonglong2 xv = *reinterpret_cast<const ulonglong2*>(xrow + bi);

                unsigned long long pA = ONE2;
#pragma unroll
                for (int oi = 0; oi < OT; oi++) {
                    ulonglong2 e = *reinterpret_cast<const ulonglong2*>(erow + (size_t)oi * NI + bi);
                    ulonglong2 m = *reinterpret_cast<const ulonglong2*>(&mu_s[oi * NI + bi]);
                    ulonglong2 s = *reinterpret_cast<const ulonglong2*>(&sg_s[oi * NI + bi]);
                    BODY2(e.x, m.x, s.x, xv.x, oi)
                    BODY2(e.y, m.y, s.y, xv.y, oi)
                }
                float al, ah;
                f2_unpack(pA, al, ah);
                sr += __logf(al) + __logf(ah);
            }

            // reduce dots, add sampled bias, emit out[b,o]; lane0 bias stats
#pragma unroll
            for (int oi = 0; oi < OT; oi++) {
                float vl, vh;
                f2_unpack(d2[oi], vl, vh);
                float v = vl + vh;
#pragma unroll
                for (int off = 16; off; off >>= 1)
                    v += __shfl_down_sync(0xffffffffu, v, off);
                if (lane == 0) {
                    int o    = o_base + oi;
                    float bs = log1pf(__expf(brho[o]));
                    float eb = epsb[b * NO + o];
                    float bv = fmaf(bs, eb, bmu[o]);
                    out[b * NO + o] = v + bv;
                    pb += -__logf(bs) - 0.5f * eb * eb;
                    float tb = bv * bv;
                    stb += tb;
                    float dfb = fmaf(tb, -C2, KP);
                    sr += fmaxf(dfb, 0.f);
                    float fdb = fabsf(dfb);
                    if (fdb < 15.f) sr += log1pf(__expf(-fdb));
                }
            }
        }
#undef BODY2

        // collapse packed accumulators; warp-level reduce; store per-item/warp
        float s0l, s0h, s1l, s1h;
        f2_unpack(stA, s0l, s0h);
        f2_unpack(seA, s1l, s1h);
        float acc[5];
        acc[0] = s0l + s0h + stb;   // st
        acc[1] = sr;                // softplus sum
        acc[2] = s1l + s1h;         // se
        acc[3] = pb;                // bias posterior
        acc[4] = lsig;              // log sigma (each tile staged 4x -> coeff 16)
#pragma unroll
        for (int q = 0; q < 5; q++) {
#pragma unroll
            for (int off = 16; off; off >>= 1)
                acc[q] += __shfl_down_sync(0xffffffffu, acc[q], off);
        }
        if (lane == 0) {
            double* p = g_part + ((size_t)item * 8 + warp) * 5;
#pragma unroll
            for (int q = 0; q < 5; q++) p[q] = (double)acc[q];
        }
    }

    // ---- completion + last-block finalize (fixed-order double reduction) ----
    __threadfence();
    if (t == 0) {
        int old = atomicAdd(&g_done, 1);
        s_last = (old == GRID - 1) ? 1 : 0;
    }
    __syncthreads();
    if (!s_last) return;
    __threadfence();

    double a[5] = {0, 0, 0, 0, 0};
    for (int i = t; i < NITEMS * 8; i += 256) {
        const double* p = g_part + (size_t)i * 5;
#pragma unroll
        for (int q = 0; q < 5; q++) a[q] += p[q];
    }

    double tot[5];
#pragma unroll
    for (int q = 0; q < 5; q++) {
        __syncthreads();
        dred[t] = a[q];
        __syncthreads();
        for (int s = 128; s > 0; s >>= 1) {
            if (t < s) dred[t] += dred[t + s];
            __syncthreads();
        }
        tot[q] = dred[0];
    }
    if (t == 0) {
        const double c   = 0.9189385332046727;     // log(sqrt(2*pi))
        const double l05 = -0.6931471805599453;    // log(0.5)
        const double Nw  = 67108864.0;             // B*O*I
        const double Nb2 = 65536.0;                // B*O
        double lp    = (Nw + Nb2) * (l05 - c) - 0.5 * tot[0] + tot[1];
        // each o-tile staged by its 4 items -> coefficient 64/4 = 16
        double lpost = -(Nw + Nb2) * c - 16.0 * tot[4] - 0.5 * tot[2] + tot[3];
        out[NB * NO]     = (float)lp;
        out[NB * NO + 1] = (float)lpost;
        g_work = 0;                                 // reset for next replay
        g_done = 0;
    }
}

// ---------------------------------------------------------------------------
extern "C" void kernel_launch(void* const* d_in, const int* in_sizes, int n_in,
                              void* d_out, int out_size)
{
    const float* x    = (const float*)d_in[0];   // (64,1024)
    const float* wmu  = (const float*)d_in[1];   // (1024,1024)
    const float* wrho = (const float*)d_in[2];   // (1024,1024)
    const float* bmu  = (const float*)d_in[3];   // (1024,)
    const float* brho = (const float*)d_in[4];   // (1024,)
    const float* epsw = (const float*)d_in[5];   // (64,1024,1024)
    const float* epsb = (const float*)d_in[6];   // (64,1024)
    float* out = (float*)d_out;                  // 65536 + 2

    main_kernel<<<GRID, 256>>>(x, wmu, wrho, bmu, brho, epsw, epsb, out);
}

// round 16
// speedup vs baseline: 1.3190x; 1.0029x over previous
#include <cuda_runtime.h>
#include <cuda_fp16.h>
#include <math.h>
#include <stdint.h>

// Problem dims (fixed by the dataset)
#define NB 64
#define NO 1024
#define NI 1024
#define OT 4                      // o-rows per block (mu/sigma staged in smem)
#define MAIN_BLOCKS (NO/OT)       // 256: one block covers all 64 batch rows

// Scratch (no allocations allowed -> __device__ globals)
__device__ double g_part[MAIN_BLOCKS][5];
__device__ int    g_counter;   // zero-init; reset by last block each run

// ---- packed f32x2 helpers (Blackwell FFMA2 path, PTX-only) ------------------
__device__ __forceinline__ unsigned long long f2_fma(unsigned long long a,
                                                     unsigned long long b,
                                                     unsigned long long c) {
    unsigned long long d;
    asm("fma.rn.f32x2 %0, %1, %2, %3;" : "=l"(d) : "l"(a), "l"(b), "l"(c));
    return d;
}
__device__ __forceinline__ unsigned long long f2_mul(unsigned long long a,
                                                     unsigned long long b) {
    unsigned long long d;
    asm("mul.rn.f32x2 %0, %1, %2;" : "=l"(d) : "l"(a), "l"(b));
    return d;
}
__device__ __forceinline__ unsigned long long f2_add(unsigned long long a,
                                                     unsigned long long b) {
    unsigned long long d;
    asm("add.rn.f32x2 %0, %1, %2;" : "=l"(d) : "l"(a), "l"(b));
    return d;
}
__device__ __forceinline__ unsigned long long f2_pack(float lo, float hi) {
    unsigned long long d;
    asm("mov.b64 %0, {%1, %2};" : "=l"(d) : "f"(lo), "f"(hi));
    return d;
}
__device__ __forceinline__ void f2_unpack(unsigned long long v, float& lo, float& hi) {
    asm("mov.b64 {%0, %1}, %2;" : "=f"(lo), "=f"(hi) : "l"(v));
}
// L2 prefetch: fire-and-forget; does NOT occupy L1tex miss-tracking slots.
__device__ __forceinline__ void pf_l2(const void* p) {
    asm volatile("prefetch.global.L2 [%0];" :: "l"(p));
}

// ---------------------------------------------------------------------------
// Main kernel (R9 structure + L2 prefetch one bb-pass ahead).
// Theory: per-SM L1-miss in-flight cap (~8KB) x DRAM latency caps BW at
// ~4.1 TB/s; prefetching eps into L2 cuts demand-miss latency ~2.5x.
// ---------------------------------------------------------------------------
__global__ __launch_bounds__(256, 2) void main_kernel(
    const float* __restrict__ x,
    const float* __restrict__ wmu,
    const float* __restrict__ wrho,
    const float* __restrict__ bmu,
    const float* __restrict__ brho,
    const float* __restrict__ epsw,
    const float* __restrict__ epsb,
    float* __restrict__ out)
{
    __shared__ float  mu_s[OT * NI];   // 16KB
    __shared__ float  sg_s[OT * NI];   // 16KB
    __shared__ float  red[256];
    __shared__ double dred[256];
    __shared__ int    is_last;

    const float KP   = 6.2146080984221914f;   // -log(0.002)
    const float C2   = 124999.5f;             // 1/(2*0.002^2) - 0.5
    const float NC2L = -180336.15876359287f;  // -C2 * log2(e)
    const float KPL2 = 8.96578433024671f;     // KP * log2(e)
    const unsigned long long NC2L2 = f2_pack(NC2L, NC2L);
    const unsigned long long KPL22 = f2_pack(KPL2, KPL2);
    const unsigned long long ONE2  = f2_pack(1.f, 1.f);

    int t      = threadIdx.x;
    int o_base = blockIdx.x * OT;
    int warp   = t >> 5, lane = t & 31;

    // prefetch bb=0's eps rows into L2 BEFORE the staging prologue
    // (each warp: its two b-rows x 16KB contiguous each = 8 prefetch insts)
    {
        const char* pA = (const char*)(epsw + ((size_t)((warp)      * NO + o_base) << 10));
        const char* pB = (const char*)(epsw + ((size_t)((warp + 8)  * NO + o_base) << 10));
#pragma unroll
        for (int q = 0; q < 4; q++) {
            pf_l2(pA + q * 4096 + lane * 128);
            pf_l2(pB + q * 4096 + lane * 128);
        }
    }

    // stage mu and sigma=softplus(rho) into smem, accumulating sum(log sigma)
    float lsig = 0.f;
#pragma unroll
    for (int k = 0; k < 4; k++) {
        int f   = t + k * 256;
        int row = f >> 8;
        int col = (f & 255) << 2;
        float4 m = *reinterpret_cast<const float4*>(wmu + (size_t)(o_base + row) * NI + col);
        float4 r = *reinterpret_cast<const float4*>(wrho + (size_t)(o_base + row) * NI + col);
        float4 s;
        s.x = log1pf(__expf(r.x));
        s.y = log1pf(__expf(r.y));
        s.z = log1pf(__expf(r.z));
        s.w = log1pf(__expf(r.w));
        lsig += __logf(s.x) + __logf(s.y) + __logf(s.z) + __logf(s.w);
        *reinterpret_cast<float4*>(&mu_s[row * NI + col]) = m;
        *reinterpret_cast<float4*>(&sg_s[row * NI + col]) = s;
    }
    __syncthreads();

    // lean accumulator chains (dep chains hidden behind memory latency)
    unsigned long long stA = 0ull;   // sum w^2
    unsigned long long seA = 0ull;   // sum eps^2
    float sr = 0.f;                  // sum softplus(df)
    float pb = 0.f;                  // bias posterior extras
    float st_bias = 0.f;             // bias w^2 (scalar, tiny)

#define BODY2(E2, M2, S2, X2, DACC, PQ)                           \
    {                                                             \
        unsigned long long w2 = f2_fma((S2), (E2), (M2));         \
        DACC   = f2_fma(w2, (X2), DACC);                          \
        seA    = f2_fma((E2), (E2), seA);                         \
        unsigned long long t2 = f2_mul(w2, w2);                   \
        stA = f2_add(stA, t2);                                    \
        unsigned long long u2 = f2_fma(t2, NC2L2, KPL22);         \
        float ul, uh; f2_unpack(u2, ul, uh);                      \
        float2 ef = __half22float2(h2exp2(__floats2half2_rn(ul, uh))); \
        unsigned long long ee = f2_pack(ef.x, ef.y);              \
        PQ = f2_fma(PQ, ee, PQ);                                  \
    }

    for (int bb = 0; bb < 4; bb++) {
        int bA = bb * 16 + warp;       // two b-rows per warp per pass
        int bB = bA + 8;

        // prefetch NEXT pass's eps rows into L2 (one full pass of lead time)
        if (bb < 3) {
            const char* pA = (const char*)(epsw + ((size_t)((bA + 16) * NO + o_base) << 10));
            const char* pB = (const char*)(epsw + ((size_t)((bB + 16) * NO + o_base) << 10));
#pragma unroll
            for (int q = 0; q < 4; q++) {
                pf_l2(pA + q * 4096 + lane * 128);
                pf_l2(pB + q * 4096 + lane * 128);
            }
        }

        unsigned long long dA[OT], dB[OT];
#pragma unroll
        for (int oi = 0; oi < OT; oi++) { dA[oi] = 0ull; dB[oi] = 0ull; }

        const float* xrA = x + (size_t)bA * NI;
        const float* xrB = x + (size_t)bB * NI;
        const float* erA = epsw + (((size_t)(bA * NO + o_base)) << 10);
        const float* erB = epsw + (((size_t)(bB * NO + o_base)) << 10);

        for (int j = 0; j < 8; j++) {
            int bi = (j << 7) + (lane << 2);

            // 8 independent eps LDG.128 batched up front
            ulonglong2 eA[OT], eB[OT];
#pragma unroll
            for (int oi = 0; oi < OT; oi++)
                eA[oi] = *reinterpret_cast<const ulonglong2*>(erA + (size_t)oi * NI + bi);
#pragma unroll
            for (int oi = 0; oi < OT; oi++)
                eB[oi] = *reinterpret_cast<const ulonglong2*>(erB + (size_t)oi * NI + bi);

            ulonglong2 xvA = *reinterpret_cast<const ulonglong2*>(xrA + bi);
            ulonglong2 xvB = *reinterpret_cast<const ulonglong2*>(xrB + bi);

            unsigned long long pA = ONE2, pB = ONE2;   // 8 factors/slot each
#pragma unroll
            for (int oi = 0; oi < OT; oi++) {
                ulonglong2 m = *reinterpret_cast<const ulonglong2*>(&mu_s[oi * NI + bi]);
                ulonglong2 s = *reinterpret_cast<const ulonglong2*>(&sg_s[oi * NI + bi]);
                BODY2(eA[oi].x, m.x, s.x, xvA.x, dA[oi], pA)
                BODY2(eA[oi].y, m.y, s.y, xvA.y, dA[oi], pA)
                BODY2(eB[oi].x, m.x, s.x, xvB.x, dB[oi], pB)
                BODY2(eB[oi].y, m.y, s.y, xvB.y, dB[oi], pB)
            }
            float al, ah, bl, bh2;
            f2_unpack(pA, al, ah);
            f2_unpack(pB, bl, bh2);
            sr += __logf(al) + __logf(ah) + __logf(bl) + __logf(bh2);
        }

        // reduce dots, add sampled bias, emit out[b,o]; lane0 folds bias stats
#pragma unroll
        for (int oi = 0; oi < OT; oi++) {
#pragma unroll
            for (int half = 0; half < 2; half++) {
                int b = half ? bB : bA;
                float vl, vh;
                f2_unpack(half ? dB[oi] : dA[oi], vl, vh);
                float v = vl + vh;
#pragma unroll
                for (int off = 16; off; off >>= 1)
                    v += __shfl_down_sync(0xffffffffu, v, off);
                if (lane == 0) {
                    int o    = o_base + oi;
                    float bs = log1pf(expf(brho[o]));          // softplus(bias_rho)
                    float eb = epsb[b * NO + o];
                    float bv = fmaf(bs, eb, bmu[o]);           // sampled bias
                    out[b * NO + o] = v + bv;
                    pb += -logf(bs) - 0.5f * eb * eb;          // bias posterior
                    float tb = bv * bv;                        // bias prior
                    st_bias += tb;
                    float dfb = fmaf(tb, -C2, KP);
                    sr += fmaxf(dfb, 0.f);
                    float fdb = fabsf(dfb);
                    if (fdb < 15.f) sr += log1pf(expf(-fdb));
                }
            }
        }
    }
#undef BODY2

    // collapse packed accumulators to scalars
    float s0l, s0h, s1l, s1h;
    f2_unpack(stA, s0l, s0h);
    f2_unpack(seA, s1l, s1h);
    float st = s0l + s0h + st_bias;
    float se = s1l + s1h;

    // block reduction of the 5 accumulators -> deterministic double partials
    float acc[5] = {st, sr, se, pb, lsig};
#pragma unroll
    for (int q = 0; q < 5; q++) {
        __syncthreads();
        red[t] = acc[q];
        __syncthreads();
        for (int s = 128; s > 0; s >>= 1) {
            if (t < s) red[t] += red[t + s];
            __syncthreads();
        }
        if (t == 0) g_part[blockIdx.x][q] = (double)red[0];
    }

    // ---- last-block finalize (deterministic fixed-order double reduction) ----
    __threadfence();
    if (t == 0) {
        int old = atomicAdd(&g_counter, 1);
        is_last = (old == MAIN_BLOCKS - 1) ? 1 : 0;
    }
    __syncthreads();
    if (!is_last) return;
    __threadfence();

    double a[5] = {0, 0, 0, 0, 0};
    for (int i = t; i < MAIN_BLOCKS; i += 256)
#pragma unroll
        for (int q = 0; q < 5; q++) a[q] += g_part[i][q];

    double tot[5];
#pragma unroll
    for (int q = 0; q < 5; q++) {
        __syncthreads();
        dred[t] = a[q];
        __syncthreads();
        for (int s = 128; s > 0; s >>= 1) {
            if (t < s) dred[t] += dred[t + s];
            __syncthreads();
        }
        tot[q] = dred[0];
    }
    if (t == 0) {
        const double c   = 0.9189385332046727;     // log(sqrt(2*pi))
        const double l05 = -0.6931471805599453;    // log(0.5)
        const double Nw  = 67108864.0;             // B*O*I
        const double Nb2 = 65536.0;                // B*O
        double lp    = (Nw + Nb2) * (l05 - c) - 0.5 * tot[0] + tot[1];
        // each o-tile staged exactly once -> coefficient B = 64
        double lpost = -(Nw + Nb2) * c - 64.0 * tot[4] - 0.5 * tot[2] + tot[3];
        out[NB * NO]     = (float)lp;
        out[NB * NO + 1] = (float)lpost;
        g_counter = 0;                              // reset for next graph replay
    }
}

// ---------------------------------------------------------------------------
extern "C" void kernel_launch(void* const* d_in, const int* in_sizes, int n_in,
                              void* d_out, int out_size)
{
    const float* x    = (const float*)d_in[0];   // (64,1024)
    const float* wmu  = (const float*)d_in[1];   // (1024,1024)
    const float* wrho = (const float*)d_in[2];   // (1024,1024)
    const float* bmu  = (const float*)d_in[3];   // (1024,)
    const float* brho = (const float*)d_in[4];   // (1024,)
    const float* epsw = (const float*)d_in[5];   // (64,1024,1024)
    const float* epsb = (const float*)d_in[6];   // (64,1024)
    float* out = (float*)d_out;                  // 65536 + 2

    main_kernel<<<MAIN_BLOCKS, 256>>>(x, wmu, wrho, bmu, brho, epsw, epsb, out);
}

// round 17
// speedup vs baseline: 1.6664x; 1.2634x over previous
#include <cuda_runtime.h>
#include <cuda_fp16.h>
#include <math.h>
#include <stdint.h>

// Problem dims (fixed by the dataset)
#define NB 64
#define NO 1024
#define NI 1024
#define OT 4                      // o-rows per block (mu/sigma staged in smem)
#define MAIN_BLOCKS (NO/OT)       // 256: one block covers all 64 batch rows

// Scratch (no allocations allowed -> __device__ globals)
__device__ double g_part[MAIN_BLOCKS][5];
__device__ int    g_counter;   // zero-init; reset by last block each run

// ---- packed f32x2 helpers (Blackwell FFMA2 path, PTX-only) ------------------
__device__ __forceinline__ unsigned long long f2_fma(unsigned long long a,
                                                     unsigned long long b,
                                                     unsigned long long c) {
    unsigned long long d;
    asm("fma.rn.f32x2 %0, %1, %2, %3;" : "=l"(d) : "l"(a), "l"(b), "l"(c));
    return d;
}
__device__ __forceinline__ unsigned long long f2_mul(unsigned long long a,
                                                     unsigned long long b) {
    unsigned long long d;
    asm("mul.rn.f32x2 %0, %1, %2;" : "=l"(d) : "l"(a), "l"(b));
    return d;
}
__device__ __forceinline__ unsigned long long f2_add(unsigned long long a,
                                                     unsigned long long b) {
    unsigned long long d;
    asm("add.rn.f32x2 %0, %1, %2;" : "=l"(d) : "l"(a), "l"(b));
    return d;
}
__device__ __forceinline__ unsigned long long f2_pack(float lo, float hi) {
    unsigned long long d;
    asm("mov.b64 %0, {%1, %2};" : "=l"(d) : "f"(lo), "f"(hi));
    return d;
}
__device__ __forceinline__ void f2_unpack(unsigned long long v, float& lo, float& hi) {
    asm("mov.b64 {%0, %1}, %2;" : "=f"(lo), "=f"(hi) : "l"(v));
}
// L2 prefetch: fire-and-forget; does NOT occupy L1tex miss-tracking slots.
__device__ __forceinline__ void pf_l2(const void* p) {
    asm volatile("prefetch.global.L2 [%0];" :: "l"(p));
}

// ---------------------------------------------------------------------------
// Main kernel: R9 structure + SHORT-distance L2 prefetch (j+2, i.e. +1KB).
// R16 proved latency-shortening raises the DRAM engine rate (4.2->4.7TB/s)
// but its pass-length lead time overflowed L2 and double-fetched (+50%
// traffic). This round: in-flight prefetch window ~19MB chip-wide, fully
// L2-resident; traffic stays 272MB while demand misses hit L2 (~240cyc).
// ---------------------------------------------------------------------------
__global__ __launch_bounds__(256, 2) void main_kernel(
    const float* __restrict__ x,
    const float* __restrict__ wmu,
    const float* __restrict__ wrho,
    const float* __restrict__ bmu,
    const float* __restrict__ brho,
    const float* __restrict__ epsw,
    const float* __restrict__ epsb,
    float* __restrict__ out)
{
    __shared__ float  mu_s[OT * NI];   // 16KB
    __shared__ float  sg_s[OT * NI];   // 16KB
    __shared__ float  red[256];
    __shared__ double dred[256];
    __shared__ int    is_last;

    const float KP   = 6.2146080984221914f;   // -log(0.002)
    const float C2   = 124999.5f;             // 1/(2*0.002^2) - 0.5
    const float NC2L = -180336.15876359287f;  // -C2 * log2(e)
    const float KPL2 = 8.96578433024671f;     // KP * log2(e)
    const unsigned long long NC2L2 = f2_pack(NC2L, NC2L);
    const unsigned long long KPL22 = f2_pack(KPL2, KPL2);
    const unsigned long long ONE2  = f2_pack(1.f, 1.f);

    int t      = threadIdx.x;
    int o_base = blockIdx.x * OT;
    int warp   = t >> 5, lane = t & 31;

    // stage mu and sigma=softplus(rho) into smem, accumulating sum(log sigma)
    float lsig = 0.f;
#pragma unroll
    for (int k = 0; k < 4; k++) {
        int f   = t + k * 256;
        int row = f >> 8;
        int col = (f & 255) << 2;
        float4 m = *reinterpret_cast<const float4*>(wmu + (size_t)(o_base + row) * NI + col);
        float4 r = *reinterpret_cast<const float4*>(wrho + (size_t)(o_base + row) * NI + col);
        float4 s;
        s.x = log1pf(__expf(r.x));
        s.y = log1pf(__expf(r.y));
        s.z = log1pf(__expf(r.z));
        s.w = log1pf(__expf(r.w));
        lsig += __logf(s.x) + __logf(s.y) + __logf(s.z) + __logf(s.w);
        *reinterpret_cast<float4*>(&mu_s[row * NI + col]) = m;
        *reinterpret_cast<float4*>(&sg_s[row * NI + col]) = s;
    }
    __syncthreads();

    // lean accumulator chains (dep chains hidden behind memory latency)
    unsigned long long stA = 0ull;   // sum w^2
    unsigned long long seA = 0ull;   // sum eps^2
    float sr = 0.f;                  // sum softplus(df)
    float pb = 0.f;                  // bias posterior extras
    float st_bias = 0.f;             // bias w^2 (scalar, tiny)

    // predicate: 4 lanes per warp issue prefetches (one per 128B line)
    bool pf_lane = ((lane & 7) == 0);

#define BODY2(E2, M2, S2, X2, DACC, PQ)                           \
    {                                                             \
        unsigned long long w2 = f2_fma((S2), (E2), (M2));         \
        DACC   = f2_fma(w2, (X2), DACC);                          \
        seA    = f2_fma((E2), (E2), seA);                         \
        unsigned long long t2 = f2_mul(w2, w2);                   \
        stA = f2_add(stA, t2);                                    \
        unsigned long long u2 = f2_fma(t2, NC2L2, KPL22);         \
        float ul, uh; f2_unpack(u2, ul, uh);                      \
        float2 ef = __half22float2(h2exp2(__floats2half2_rn(ul, uh))); \
        unsigned long long ee = f2_pack(ef.x, ef.y);              \
        PQ = f2_fma(PQ, ee, PQ);                                  \
    }

    for (int bb = 0; bb < 4; bb++) {
        int bA = bb * 16 + warp;       // two b-rows per warp per pass
        int bB = bA + 8;

        unsigned long long dA[OT], dB[OT];
#pragma unroll
        for (int oi = 0; oi < OT; oi++) { dA[oi] = 0ull; dB[oi] = 0ull; }

        const float* xrA = x + (size_t)bA * NI;
        const float* xrB = x + (size_t)bB * NI;
        const float* erA = epsw + (((size_t)(bA * NO + o_base)) << 10);
        const float* erB = epsw + (((size_t)(bB * NO + o_base)) << 10);

        for (int j = 0; j < 8; j++) {
            int bi = (j << 7) + (lane << 2);

            // 8 independent eps LDG.128 batched up front
            ulonglong2 eA[OT], eB[OT];
#pragma unroll
            for (int oi = 0; oi < OT; oi++)
                eA[oi] = *reinterpret_cast<const ulonglong2*>(erA + (size_t)oi * NI + bi);
#pragma unroll
            for (int oi = 0; oi < OT; oi++)
                eB[oi] = *reinterpret_cast<const ulonglong2*>(erB + (size_t)oi * NI + bi);

            // L2 prefetch for iteration j+2 (same rows, +1KB): short lead,
            // tiny in-flight window, no L2 eviction, no double-fetch.
            if (pf_lane && j < 6) {
#pragma unroll
                for (int oi = 0; oi < OT; oi++) {
                    pf_l2(erA + (size_t)oi * NI + bi + 256);
                    pf_l2(erB + (size_t)oi * NI + bi + 256);
                }
            }

            ulonglong2 xvA = *reinterpret_cast<const ulonglong2*>(xrA + bi);
            ulonglong2 xvB = *reinterpret_cast<const ulonglong2*>(xrB + bi);

            unsigned long long pA = ONE2, pB = ONE2;   // 8 factors/slot each
#pragma unroll
            for (int oi = 0; oi < OT; oi++) {
                ulonglong2 m = *reinterpret_cast<const ulonglong2*>(&mu_s[oi * NI + bi]);
                ulonglong2 s = *reinterpret_cast<const ulonglong2*>(&sg_s[oi * NI + bi]);
                BODY2(eA[oi].x, m.x, s.x, xvA.x, dA[oi], pA)
                BODY2(eA[oi].y, m.y, s.y, xvA.y, dA[oi], pA)
                BODY2(eB[oi].x, m.x, s.x, xvB.x, dB[oi], pB)
                BODY2(eB[oi].y, m.y, s.y, xvB.y, dB[oi], pB)
            }
            float al, ah, bl, bh2;
            f2_unpack(pA, al, ah);
            f2_unpack(pB, bl, bh2);
            sr += __logf(al) + __logf(ah) + __logf(bl) + __logf(bh2);
        }

        // reduce dots, add sampled bias, emit out[b,o]; lane0 folds bias stats
#pragma unroll
        for (int oi = 0; oi < OT; oi++) {
#pragma unroll
            for (int half = 0; half < 2; half++) {
                int b = half ? bB : bA;
                float vl, vh;
                f2_unpack(half ? dB[oi] : dA[oi], vl, vh);
                float v = vl + vh;
#pragma unroll
                for (int off = 16; off; off >>= 1)
                    v += __shfl_down_sync(0xffffffffu, v, off);
                if (lane == 0) {
                    int o    = o_base + oi;
                    float bs = log1pf(expf(brho[o]));          // softplus(bias_rho)
                    float eb = epsb[b * NO + o];
                    float bv = fmaf(bs, eb, bmu[o]);           // sampled bias
                    out[b * NO + o] = v + bv;
                    pb += -logf(bs) - 0.5f * eb * eb;          // bias posterior
                    float tb = bv * bv;                        // bias prior
                    st_bias += tb;
                    float dfb = fmaf(tb, -C2, KP);
                    sr += fmaxf(dfb, 0.f);
                    float fdb = fabsf(dfb);
                    if (fdb < 15.f) sr += log1pf(expf(-fdb));
                }
            }
        }
    }
#undef BODY2

    // collapse packed accumulators to scalars
    float s0l, s0h, s1l, s1h;
    f2_unpack(stA, s0l, s0h);
    f2_unpack(seA, s1l, s1h);
    float st = s0l + s0h + st_bias;
    float se = s1l + s1h;

    // block reduction of the 5 accumulators -> deterministic double partials
    float acc[5] = {st, sr, se, pb, lsig};
#pragma unroll
    for (int q = 0; q < 5; q++) {
        __syncthreads();
        red[t] = acc[q];
        __syncthreads();
        for (int s = 128; s > 0; s >>= 1) {
            if (t < s) red[t] += red[t + s];
            __syncthreads();
        }
        if (t == 0) g_part[blockIdx.x][q] = (double)red[0];
    }

    // ---- last-block finalize (deterministic fixed-order double reduction) ----
    __threadfence();
    if (t == 0) {
        int old = atomicAdd(&g_counter, 1);
        is_last = (old == MAIN_BLOCKS - 1) ? 1 : 0;
    }
    __syncthreads();
    if (!is_last) return;
    __threadfence();

    double a[5] = {0, 0, 0, 0, 0};
    for (int i = t; i < MAIN_BLOCKS; i += 256)
#pragma unroll
        for (int q = 0; q < 5; q++) a[q] += g_part[i][q];

    double tot[5];
#pragma unroll
    for (int q = 0; q < 5; q++) {
        __syncthreads();
        dred[t] = a[q];
        __syncthreads();
        for (int s = 128; s > 0; s >>= 1) {
            if (t < s) dred[t] += dred[t + s];
            __syncthreads();
        }
        tot[q] = dred[0];
    }
    if (t == 0) {
        const double c   = 0.9189385332046727;     // log(sqrt(2*pi))
        const double l05 = -0.6931471805599453;    // log(0.5)
        const double Nw  = 67108864.0;             // B*O*I
        const double Nb2 = 65536.0;                // B*O
        double lp    = (Nw + Nb2) * (l05 - c) - 0.5 * tot[0] + tot[1];
        // each o-tile staged exactly once -> coefficient B = 64
        double lpost = -(Nw + Nb2) * c - 64.0 * tot[4] - 0.5 * tot[2] + tot[3];
        out[NB * NO]     = (float)lp;
        out[NB * NO + 1] = (float)lpost;
        g_counter = 0;                              // reset for next graph replay
    }
}

// ---------------------------------------------------------------------------
extern "C" void kernel_launch(void* const* d_in, const int* in_sizes, int n_in,
                              void* d_out, int out_size)
{
    const float* x    = (const float*)d_in[0];   // (64,1024)
    const float* wmu  = (const float*)d_in[1];   // (1024,1024)
    const float* wrho = (const float*)d_in[2];   // (1024,1024)
    const float* bmu  = (const float*)d_in[3];   // (1024,)
    const float* brho = (const float*)d_in[4];   // (1024,)
    const float* epsw = (const float*)d_in[5];   // (64,1024,1024)
    const float* epsb = (const float*)d_in[6];   // (64,1024)
    float* out = (float*)d_out;                  // 65536 + 2

    main_kernel<<<MAIN_BLOCKS, 256>>>(x, wmu, wrho, bmu, brho, epsw, epsb, out);
}